// round 16
// baseline (speedup 1.0000x reference)
#include <cuda_runtime.h>
#include <cuda_fp16.h>
#include <cstdint>

// VQ: nearest-codebook lookup.
// Phase 1 (aa_vq_main): mma.sync fp16 GEMM -> global top-3 per row.
//   B chunks cp.async'd as fp32 from the raw codebook, converted to swizzled
//   fp16 in smem one chunk ahead (overlapped with MMA). e_sq accumulated from
//   the staged fp32. No separate prep kernel.
// Phase 2 (refine_kernel): exact fp64 on top-3 + fp32-bin tie emulation.
// x: (N=131072, C=256), code_book: (K=1024, C=256)

#define C_DIM 256
#define TILE_M 128
#define NTHREADS 256
#define MAXROWS 131072
#define TIE_GUARD 2e-6

// smem map (bytes)
#define SM_ESQ   0                      // 4KB  (esq_s[1024])
#define SM_A     4096                   // 64KB (128 rows x 512B, swizzled fp16)
#define SM_BF16  (4096 + 65536)         // 2 x 16KB converted B chunks
#define SM_STAGE (SM_BF16 + 32768)      // 2 x 32KB fp32 staging
#define SM_TOTAL (SM_STAGE + 65536)     // 167936
#define SM_MERGE SM_BF16

__device__ int4 g_top3[MAXROWS];

__device__ __forceinline__ uint32_t smem_u32(const void* p) {
    uint32_t a;
    asm("{ .reg .u64 t; cvta.to.shared.u64 t, %1; cvt.u32.u64 %0, t; }" : "=r"(a) : "l"(p));
    return a;
}
__device__ __forceinline__ void ldsm4(uint32_t* r, uint32_t addr) {
    asm volatile("ldmatrix.sync.aligned.m8n8.x4.shared.b16 {%0,%1,%2,%3}, [%4];"
        : "=r"(r[0]), "=r"(r[1]), "=r"(r[2]), "=r"(r[3]) : "r"(addr));
}
__device__ __forceinline__ void mma16816(float* d, const uint32_t* a, uint32_t b0, uint32_t b1) {
    asm volatile("mma.sync.aligned.m16n8k16.row.col.f32.f16.f16.f32 "
        "{%0,%1,%2,%3}, {%4,%5,%6,%7}, {%8,%9}, {%0,%1,%2,%3};"
        : "+f"(d[0]), "+f"(d[1]), "+f"(d[2]), "+f"(d[3])
        : "r"(a[0]), "r"(a[1]), "r"(a[2]), "r"(a[3]), "r"(b0), "r"(b1));
}
__device__ __forceinline__ void cp_async16(uint32_t dst, const void* src) {
    asm volatile("cp.async.cg.shared.global [%0], [%1], 16;" :: "r"(dst), "l"(src));
}
#define CP_COMMIT() asm volatile("cp.async.commit_group;" ::: "memory")
#define CP_WAIT1()  asm volatile("cp.async.wait_group 1;" ::: "memory")
#define CP_WAIT0()  asm volatile("cp.async.wait_group 0;" ::: "memory")

__device__ __forceinline__ uint32_t pkh(__half lo, __half hi) {
    return ((uint32_t)__half_as_ushort(hi) << 16) | (uint32_t)__half_as_ushort(lo);
}

// ---------------- phase 1 ----------------
__global__ __launch_bounds__(NTHREADS)
void aa_vq_main(const float* __restrict__ x, const float* __restrict__ cb,
                int NROWS, int K)
{
    extern __shared__ char smem[];
    const uint32_t sb = smem_u32(smem);
    float* esq_s = (float*)(smem + SM_ESQ);
    const int tid = threadIdx.x;
    const int wid = tid >> 5, l = tid & 31;
    const int Wm = wid >> 1, Wn = wid & 1;      // 4m x 2n warp grid (R14 layout)
    const int row0 = blockIdx.x * TILE_M;
    const int nch = (K / 128) * 4;              // 32 for K=1024

    // ---- staging loader: chunk c (tile=c>>2, kc=c&3) fp32 -> stage[c&1] ----
    auto stage_load = [&](int c) {
        const int tile = c >> 2, kc = c & 3;
        const uint32_t dstbase = sb + SM_STAGE + (uint32_t)(c & 1) * 32768u;
#pragma unroll
        for (int it = 0; it < 8; ++it) {
            int i = tid + it * NTHREADS;        // 0..2047 (16B units)
            int n = i >> 4;
            int q = i & 15;
            const float* src = cb + ((size_t)(tile * 128 + n) * C_DIM + kc * 64 + q * 4);
            cp_async16(dstbase + (uint32_t)i * 16u, src);
        }
    };
    // ---- convert chunk c: stage[c&1] fp32 -> Bf16[c&1] swizzled; accumulate esq ----
    auto convert_chunk = [&](int c) {
        const int tile1 = c >> 2, kc1 = c & 3;
        const char* stg = smem + SM_STAGE + (c & 1) * 32768;
        char* bf = smem + SM_BF16 + (c & 1) * 16384;
#pragma unroll
        for (int u = tid * 4; u < tid * 4 + 4; ++u) {   // 1024 units total
            int n = u >> 3, jj = u & 7;
            float4 v0 = *(const float4*)(stg + n * 256 + jj * 32);
            float4 v1 = *(const float4*)(stg + n * 256 + jj * 32 + 16);
            uint4 o;
            o.x = pkh(__float2half(v0.x), __float2half(v0.y));
            o.y = pkh(__float2half(v0.z), __float2half(v0.w));
            o.z = pkh(__float2half(v1.x), __float2half(v1.y));
            o.w = pkh(__float2half(v1.z), __float2half(v1.w));
            *(uint4*)(bf + n * 128 + ((jj ^ (n & 7)) << 4)) = o;
        }
        if (tid < 128) {
            const int n = tid;
            float s = 0.0f;
#pragma unroll
            for (int q = 0; q < 16; ++q) {
                float4 v = *(const float4*)(stg + n * 256 + q * 16);
                s = fmaf(v.x, v.x, s); s = fmaf(v.y, v.y, s);
                s = fmaf(v.z, v.z, s); s = fmaf(v.w, v.w, s);
            }
            const int idx = tile1 * 128 + n;
            esq_s[idx] = (kc1 == 0) ? s : (esq_s[idx] + s);
        }
    };

    // ---- prologue: stage chunks 0,1; build A; convert chunk 0 ----
    stage_load(0); CP_COMMIT();
    stage_load(1); CP_COMMIT();

#pragma unroll 4
    for (int it = 0; it < 32; ++it) {
        int i4 = tid + it * NTHREADS;    // 8192 float4s = 128 rows x 64
        int r = i4 >> 6;
        int c0 = (i4 & 63) * 4;
        int rr = row0 + r; if (rr >= NROWS) rr = NROWS - 1;
        float4 v = *(const float4*)(x + (size_t)rr * C_DIM + c0);
        uint32_t byte = (uint32_t)(r * 512 + (((c0 >> 3) ^ (r & 7)) << 4) + (c0 & 7) * 2);
        *(uint32_t*)(smem + SM_A + byte)     = pkh(__float2half(v.x), __float2half(v.y));
        *(uint32_t*)(smem + SM_A + byte + 4) = pkh(__float2half(v.z), __float2half(v.w));
    }

    CP_WAIT1();          // chunk 0 staged
    __syncthreads();
    convert_chunk(0);
    __syncthreads();

    // ---- per-lane ldmatrix address bases (R14-verified) ----
    uint32_t aBase[2], a7[2];
    const uint32_t jAadd = (uint32_t)((l >> 4) & 1);
#pragma unroll
    for (int mt = 0; mt < 2; ++mt) {
        int rA = Wm * 32 + mt * 16 + ((l >> 3) & 1) * 8 + (l & 7);
        aBase[mt] = sb + SM_A + (uint32_t)rA * 512u;
        a7[mt] = (uint32_t)(rA & 7) << 4;
    }
    uint32_t bOff[4], b7[4];
    const uint32_t jBadd = (uint32_t)((l >> 3) & 1);
#pragma unroll
    for (int ntp = 0; ntp < 4; ++ntp) {
        int nB = Wn * 64 + ntp * 16 + ((l >> 4) & 1) * 8 + (l & 7);
        bOff[ntp] = (uint32_t)nB * 128u;
        b7[ntp] = (uint32_t)(nB & 7) << 4;
    }

    float acc[2][8][4];
    float bd[4], sd[4];
    int bi[4], si[4];
#pragma unroll
    for (int s = 0; s < 4; ++s) { bd[s] = 3.4e38f; sd[s] = 3.4e38f; bi[s] = 0; si[s] = 1; }

    for (int ch = 0; ch < nch; ++ch) {
        // stage chunk ch+2 into stage[ch&1] (chunk ch's fp32 already converted)
        if (ch + 2 < nch) { stage_load(ch + 2); CP_COMMIT(); }
        if (ch + 1 < nch) { if (ch + 2 < nch) CP_WAIT1(); else CP_WAIT0(); }
        __syncthreads();     // staging of chunk ch+1 visible to all threads

        // convert chunk ch+1 (overlaps with MMA below in the same phase)
        if (ch + 1 < nch) convert_chunk(ch + 1);

        const int kc = ch & 3, tile = ch >> 2;
        if (kc == 0) {
#pragma unroll
            for (int mt = 0; mt < 2; ++mt)
#pragma unroll
                for (int nt = 0; nt < 8; ++nt)
#pragma unroll
                    for (int q = 0; q < 4; ++q) acc[mt][nt][q] = 0.0f;
        }
        const uint32_t bufb = sb + SM_BF16 + (uint32_t)(ch & 1) * 16384u;

#pragma unroll
        for (int ks = 0; ks < 4; ++ks) {
            uint32_t a[2][4];
            const uint32_t jxA = (uint32_t)((kc * 8 + ks * 2 + jAadd) << 4);
#pragma unroll
            for (int mt = 0; mt < 2; ++mt)
                ldsm4(a[mt], aBase[mt] + (jxA ^ a7[mt]));

            const uint32_t jxB = (uint32_t)((ks * 2 + jBadd) << 4);
#pragma unroll
            for (int ntp = 0; ntp < 4; ++ntp) {
                uint32_t bf[4];
                ldsm4(bf, bufb + bOff[ntp] + (jxB ^ b7[ntp]));
#pragma unroll
                for (int mt = 0; mt < 2; ++mt) {
#pragma unroll
                    for (int sub = 0; sub < 2; ++sub)
                        mma16816(acc[mt][ntp * 2 + sub], a[mt], bf[2 * sub], bf[2 * sub + 1]);
                }
            }
        }

        if (kc == 3) {
            // per-source top-2 update (esq for this tile completed last iteration)
            const int cbase = tile * 128 + Wn * 64 + 2 * (l & 3);
#pragma unroll
            for (int mt = 0; mt < 2; ++mt) {
#pragma unroll
                for (int rh = 0; rh < 2; ++rh) {
                    const int s = mt * 2 + rh;
                    float lbd = bd[s], lsd = sd[s];
                    int lbi = bi[s], lsi = si[s];
#pragma unroll
                    for (int nt = 0; nt < 8; ++nt) {
                        const int code = cbase + nt * 8;
                        float d0 = fmaf(-2.0f, acc[mt][nt][rh * 2 + 0], esq_s[code]);
                        float d1 = fmaf(-2.0f, acc[mt][nt][rh * 2 + 1], esq_s[code + 1]);
                        if (d0 < lbd) { lsd = lbd; lsi = lbi; lbd = d0; lbi = code; }
                        else if (d0 < lsd) { lsd = d0; lsi = code; }
                        if (d1 < lbd) { lsd = lbd; lsi = lbi; lbd = d1; lbi = code + 1; }
                        else if (d1 < lsd) { lsd = d1; lsi = code + 1; }
                    }
                    bd[s] = lbd; sd[s] = lsd; bi[s] = lbi; si[s] = lsi;
                }
            }
        }
        __syncthreads();   // convert results visible; frees Bf16/stage slots
    }

    // ---- merge: 8 sources x top-2 per row -> global top-3 ----
    float* md = (float*)(smem + SM_MERGE);          // [128][8][2] = 8KB
    int*   mi = (int*)(smem + SM_MERGE + 8192);
#pragma unroll
    for (int mt = 0; mt < 2; ++mt) {
#pragma unroll
        for (int rh = 0; rh < 2; ++rh) {
            const int s = mt * 2 + rh;
            const int r = Wm * 32 + mt * 16 + rh * 8 + (l >> 2);
            const int slot = (l & 3) * 2 + Wn;      // 0..7
            md[(r * 8 + slot) * 2 + 0] = bd[s];
            md[(r * 8 + slot) * 2 + 1] = sd[s];
            mi[(r * 8 + slot) * 2 + 0] = bi[s];
            mi[(r * 8 + slot) * 2 + 1] = si[s];
        }
    }
    __syncthreads();
    if (tid < TILE_M) {
        float b1 = 3.4e38f, b2 = 3.4e38f, b3 = 3.4e38f;
        int j1 = 0, j2 = 1, j3 = 2;
#pragma unroll 4
        for (int t = 0; t < 16; ++t) {
            float d = md[tid * 16 + t];
            int ii = mi[tid * 16 + t];
            if (d < b1 || (d == b1 && ii < j1)) {
                b3 = b2; j3 = j2; b2 = b1; j2 = j1; b1 = d; j1 = ii;
            } else if (d < b2 || (d == b2 && ii < j2)) {
                b3 = b2; j3 = j2; b2 = d; j2 = ii;
            } else if (d < b3 || (d == b3 && ii < j3)) {
                b3 = d; j3 = ii;
            }
        }
        int a = j1, b = j2, c = j3, t;
        if (a > b) { t = a; a = b; b = t; }
        if (b > c) { t = b; b = c; c = t; }
        if (a > b) { t = a; a = b; b = t; }
        const int row = row0 + tid;
        if (row < NROWS) g_top3[row] = make_int4(a, b, c, 0);
    }
}

// ---- phase 2: exact fp64 on 3 candidates; fp32-bin tie => earlier index ----
__global__ __launch_bounds__(128, 8)
void refine_kernel(const float* __restrict__ x, const float* __restrict__ cb,
                   float* __restrict__ zq, float* __restrict__ idx_out,
                   int NROWS, int write_idx)
{
    const int warp = threadIdx.x >> 5;
    const int lane = threadIdx.x & 31;
    const int row = blockIdx.x * 4 + warp;
    if (row >= NROWS) return;

    const int4 cand = g_top3[row];   // indices ascending
    const float* xp = x + (size_t)row * C_DIM + lane * 8;
    float4 xa = *(const float4*)(xp);
    float4 xb = *(const float4*)(xp + 4);
    const float xs[8] = {xa.x, xa.y, xa.z, xa.w, xb.x, xb.y, xb.z, xb.w};

    double d[3];
    const int ci[3] = {cand.x, cand.y, cand.z};
#pragma unroll
    for (int q = 0; q < 3; ++q) {
        const float* ep = cb + (size_t)ci[q] * C_DIM + lane * 8;
        float4 ea = *(const float4*)(ep);
        float4 eb = *(const float4*)(ep + 4);
        const float es[8] = {ea.x, ea.y, ea.z, ea.w, eb.x, eb.y, eb.z, eb.w};
        double s = 0.0;
#pragma unroll
        for (int t = 0; t < 8; ++t) {
            double df = (double)xs[t] - (double)es[t];
            s = fma(df, df, s);
        }
        d[q] = s;
    }
#pragma unroll
    for (int o = 16; o > 0; o >>= 1) {
#pragma unroll
        for (int q = 0; q < 3; ++q)
            d[q] += __shfl_down_sync(0xffffffffu, d[q], o);
    }
    int chosen;
    if (lane == 0) {
        int bidx = ci[0];
        double bval = d[0];
#pragma unroll
        for (int q = 1; q < 3; ++q) {
            float f1 = (float)bval, f2 = (float)d[q];
            bool tie = (f1 == f2) || (fabs(d[q] - bval) < (double)TIE_GUARD);
            if (!tie && d[q] < bval) { bval = d[q]; bidx = ci[q]; }
        }
        chosen = bidx;
    }
    chosen = __shfl_sync(0xffffffffu, chosen, 0);

    const float* ep = cb + (size_t)chosen * C_DIM + lane * 8;
    float* op = zq + (size_t)row * C_DIM + lane * 8;
    *(float4*)(op)     = *(const float4*)(ep);
    *(float4*)(op + 4) = *(const float4*)(ep + 4);

    if (write_idx && lane == 0) idx_out[row] = (float)chosen;
}

extern "C" void kernel_launch(void* const* d_in, const int* in_sizes, int n_in,
                              void* d_out, int out_size) {
    const float* x  = (const float*)d_in[0];
    const float* cb = (const float*)d_in[1];
    float* out = (float*)d_out;

    const int NROWS = in_sizes[0] / C_DIM;
    const int K     = in_sizes[1] / C_DIM;

    cudaFuncSetAttribute(aa_vq_main, cudaFuncAttributeMaxDynamicSharedMemorySize, SM_TOTAL);
    aa_vq_main<<<(NROWS + TILE_M - 1) / TILE_M, NTHREADS, SM_TOTAL>>>(x, cb, NROWS, K);

    const int write_idx = (out_size >= NROWS * C_DIM + NROWS) ? 1 : 0;
    refine_kernel<<<(NROWS + 3) / 4, 128>>>(x, cb, out, out + (size_t)NROWS * C_DIM,
                                            NROWS, write_idx);
}

// round 17
// speedup vs baseline: 2.2928x; 2.2928x over previous
#include <cuda_runtime.h>
#include <cuda_fp16.h>
#include <cstdint>

// VQ: nearest-codebook lookup.
// Phase 1: mma.sync fp16 single-product GEMM -> top-3 + decided flag per row.
//          (R14-benched layout: 256 thr, 4m x 2n warps, fp16 chunks via cp.async)
// Phase 2: decided rows -> pure gather; ambiguous rows -> exact fp64 on top-3
//          + fp32-bin tie emulation (verified rule, rel_err 0.0).
// x: (N=131072, C=256), code_book: (K=1024, C=256)

#define C_DIM 256
#define TILE_M 128
#define NTHREADS 256
#define MAXROWS 131072
#define MAXK 1024
#define TIE_GUARD 2e-6
#define DECIDE_GAP 2.0f

// smem map (bytes): esq 4KB | A plane 64KB | B 2 x 16KB
#define SM_ESQ 0
#define SM_A   4096
#define SM_B   (4096 + 65536)
#define SM_TOTAL (SM_B + 32768)    // 102400
#define SM_MERGE SM_B

__device__ float  g_esq[MAXK];
__device__ int4   g_top3[MAXROWS];
__device__ __half g_cbh[MAXK * C_DIM];

__device__ __forceinline__ uint32_t smem_u32(const void* p) {
    uint32_t a;
    asm("{ .reg .u64 t; cvta.to.shared.u64 t, %1; cvt.u32.u64 %0, t; }" : "=r"(a) : "l"(p));
    return a;
}
__device__ __forceinline__ void ldsm4(uint32_t* r, uint32_t addr) {
    asm volatile("ldmatrix.sync.aligned.m8n8.x4.shared.b16 {%0,%1,%2,%3}, [%4];"
        : "=r"(r[0]), "=r"(r[1]), "=r"(r[2]), "=r"(r[3]) : "r"(addr));
}
__device__ __forceinline__ void mma16816(float* d, const uint32_t* a, uint32_t b0, uint32_t b1) {
    asm volatile("mma.sync.aligned.m16n8k16.row.col.f32.f16.f16.f32 "
        "{%0,%1,%2,%3}, {%4,%5,%6,%7}, {%8,%9}, {%0,%1,%2,%3};"
        : "+f"(d[0]), "+f"(d[1]), "+f"(d[2]), "+f"(d[3])
        : "r"(a[0]), "r"(a[1]), "r"(a[2]), "r"(a[3]), "r"(b0), "r"(b1));
}
__device__ __forceinline__ void cp_async16(uint32_t dst, const void* src) {
    asm volatile("cp.async.cg.shared.global [%0], [%1], 16;" :: "r"(dst), "l"(src));
}
#define CP_COMMIT() asm volatile("cp.async.commit_group;" ::: "memory")
#define CP_WAIT1()  asm volatile("cp.async.wait_group 1;" ::: "memory")
#define CP_WAIT0()  asm volatile("cp.async.wait_group 0;" ::: "memory")

__device__ __forceinline__ uint32_t pkh(__half lo, __half hi) {
    return ((uint32_t)__half_as_ushort(hi) << 16) | (uint32_t)__half_as_ushort(lo);
}

// ---------------- prep: e_sq (fp32 exact) + codebook fp16 ----------------
__global__ void prep_cb(const float* __restrict__ cb, int K) {
    int k = blockIdx.x * 8 + (threadIdx.x >> 5);
    int lane = threadIdx.x & 31;
    if (k >= K) return;
    const float* p = cb + (size_t)k * C_DIM;
    float s = 0.0f;
    for (int c = lane; c < C_DIM; c += 32) {
        float f = p[c];
        s = fmaf(f, f, s);
        g_cbh[(size_t)k * C_DIM + c] = __float2half(f);
    }
#pragma unroll
    for (int o = 16; o > 0; o >>= 1) s += __shfl_down_sync(0xffffffffu, s, o);
    if (lane == 0) g_esq[k] = s;
}

// chunk = (tile, kc): 128 codes x 64 k (fp16) = 16KB
__device__ __forceinline__ void load_chunk(uint32_t sb, int ch, int tid) {
    const int tile = ch >> 2, kc = ch & 3;
    const uint32_t dstbase = sb + SM_B + (uint32_t)(ch & 1) * 16384u;
#pragma unroll
    for (int it = 0; it < 4; ++it) {
        int i = tid + it * NTHREADS;  // 0..1023 (16B units)
        int n = i >> 3;
        int jj = i & 7;
        const char* src = (const char*)g_cbh
                        + ((size_t)(tile * 128 + n) * C_DIM + kc * 64 + jj * 8) * 2;
        uint32_t dst = dstbase + (uint32_t)(n * 128 + (((jj ^ (n & 7)) << 4)));
        cp_async16(dst, src);
    }
}

// ---------------- phase 1 ----------------
__global__ __launch_bounds__(NTHREADS)
void vq_main(const float* __restrict__ x, int NROWS, int K)
{
    extern __shared__ char smem[];
    const uint32_t sb = smem_u32(smem);
    float* esq_s = (float*)(smem + SM_ESQ);
    const int tid = threadIdx.x;
    const int wid = tid >> 5, l = tid & 31;
    const int Wm = wid >> 1, Wn = wid & 1;      // 4m x 2n warp grid
    const int row0 = blockIdx.x * TILE_M;
    const int nch = (K / 128) * 4;              // 32 for K=1024

    for (int i = tid; i < K; i += NTHREADS) esq_s[i] = g_esq[i];

    load_chunk(sb, 0, tid);
    CP_COMMIT();

    // ---- build A plane in smem (fp16, swizzled) ----
#pragma unroll 4
    for (int it = 0; it < 32; ++it) {
        int i4 = tid + it * NTHREADS;    // 8192 float4s = 128 rows x 64
        int r = i4 >> 6;
        int c0 = (i4 & 63) * 4;
        int rr = row0 + r; if (rr >= NROWS) rr = NROWS - 1;
        float4 v = *(const float4*)(x + (size_t)rr * C_DIM + c0);
        uint32_t byte = (uint32_t)(r * 512 + (((c0 >> 3) ^ (r & 7)) << 4) + (c0 & 7) * 2);
        *(uint32_t*)(smem + SM_A + byte)     = pkh(__float2half(v.x), __float2half(v.y));
        *(uint32_t*)(smem + SM_A + byte + 4) = pkh(__float2half(v.z), __float2half(v.w));
    }

    // ---- per-lane ldmatrix address bases (R14-verified layout) ----
    uint32_t aBase[2], a7[2];
    const uint32_t jAadd = (uint32_t)((l >> 4) & 1);
#pragma unroll
    for (int mt = 0; mt < 2; ++mt) {
        int rA = Wm * 32 + mt * 16 + ((l >> 3) & 1) * 8 + (l & 7);
        aBase[mt] = sb + SM_A + (uint32_t)rA * 512u;
        a7[mt] = (uint32_t)(rA & 7) << 4;
    }
    uint32_t bOff[4], b7[4];
    const uint32_t jBadd = (uint32_t)((l >> 3) & 1);
#pragma unroll
    for (int ntp = 0; ntp < 4; ++ntp) {
        int nB = Wn * 64 + ntp * 16 + ((l >> 4) & 1) * 8 + (l & 7);
        bOff[ntp] = (uint32_t)nB * 128u;
        b7[ntp] = (uint32_t)(nB & 7) << 4;
    }

    float acc[2][8][4];
    float bd[4], sd[4];
    int bi[4], si[4];
#pragma unroll
    for (int s = 0; s < 4; ++s) { bd[s] = 3.4e38f; sd[s] = 3.4e38f; bi[s] = 0; si[s] = 1; }

    for (int ch = 0; ch < nch; ++ch) {
        if (ch + 1 < nch) { load_chunk(sb, ch + 1, tid); CP_COMMIT(); CP_WAIT1(); }
        else              { CP_WAIT0(); }
        __syncthreads();

        const int kc = ch & 3, tile = ch >> 2;
        if (kc == 0) {
#pragma unroll
            for (int mt = 0; mt < 2; ++mt)
#pragma unroll
                for (int nt = 0; nt < 8; ++nt)
#pragma unroll
                    for (int q = 0; q < 4; ++q) acc[mt][nt][q] = 0.0f;
        }
        const uint32_t bufb = sb + SM_B + (uint32_t)(ch & 1) * 16384u;

#pragma unroll
        for (int ks = 0; ks < 4; ++ks) {
            uint32_t a[2][4];
            const uint32_t jxA = (uint32_t)((kc * 8 + ks * 2 + jAadd) << 4);
#pragma unroll
            for (int mt = 0; mt < 2; ++mt)
                ldsm4(a[mt], aBase[mt] + (jxA ^ a7[mt]));

            const uint32_t jxB = (uint32_t)((ks * 2 + jBadd) << 4);
#pragma unroll
            for (int ntp = 0; ntp < 4; ++ntp) {
                uint32_t bf[4];
                ldsm4(bf, bufb + bOff[ntp] + (jxB ^ b7[ntp]));
#pragma unroll
                for (int mt = 0; mt < 2; ++mt) {
#pragma unroll
                    for (int sub = 0; sub < 2; ++sub)
                        mma16816(acc[mt][ntp * 2 + sub], a[mt], bf[2 * sub], bf[2 * sub + 1]);
                }
            }
        }

        if (kc == 3) {
            const int cbase = tile * 128 + Wn * 64 + 2 * (l & 3);
#pragma unroll
            for (int mt = 0; mt < 2; ++mt) {
#pragma unroll
                for (int rh = 0; rh < 2; ++rh) {
                    const int s = mt * 2 + rh;
                    float lbd = bd[s], lsd = sd[s];
                    int lbi = bi[s], lsi = si[s];
#pragma unroll
                    for (int nt = 0; nt < 8; ++nt) {
                        const int code = cbase + nt * 8;
                        float d0 = fmaf(-2.0f, acc[mt][nt][rh * 2 + 0], esq_s[code]);
                        float d1 = fmaf(-2.0f, acc[mt][nt][rh * 2 + 1], esq_s[code + 1]);
                        if (d0 < lbd) { lsd = lbd; lsi = lbi; lbd = d0; lbi = code; }
                        else if (d0 < lsd) { lsd = d0; lsi = code; }
                        if (d1 < lbd) { lsd = lbd; lsi = lbi; lbd = d1; lbi = code + 1; }
                        else if (d1 < lsd) { lsd = d1; lsi = code + 1; }
                    }
                    bd[s] = lbd; sd[s] = lsd; bi[s] = lbi; si[s] = lsi;
                }
            }
        }
        __syncthreads();
    }

    // ---- merge: 8 sources x top-2 per row -> global top-3 + decided flag ----
    float* md = (float*)(smem + SM_MERGE);          // [128][8][2] = 8KB
    int*   mi = (int*)(smem + SM_MERGE + 8192);
#pragma unroll
    for (int mt = 0; mt < 2; ++mt) {
#pragma unroll
        for (int rh = 0; rh < 2; ++rh) {
            const int s = mt * 2 + rh;
            const int r = Wm * 32 + mt * 16 + rh * 8 + (l >> 2);
            const int slot = (l & 3) * 2 + Wn;      // 0..7
            md[(r * 8 + slot) * 2 + 0] = bd[s];
            md[(r * 8 + slot) * 2 + 1] = sd[s];
            mi[(r * 8 + slot) * 2 + 0] = bi[s];
            mi[(r * 8 + slot) * 2 + 1] = si[s];
        }
    }
    __syncthreads();
    if (tid < TILE_M) {
        float b1 = 3.4e38f, b2 = 3.4e38f, b3 = 3.4e38f;
        int j1 = 0, j2 = 1, j3 = 2;
#pragma unroll 4
        for (int t = 0; t < 16; ++t) {
            float d = md[tid * 16 + t];
            int ii = mi[tid * 16 + t];
            if (d < b1 || (d == b1 && ii < j1)) {
                b3 = b2; j3 = j2; b2 = b1; j2 = j1; b1 = d; j1 = ii;
            } else if (d < b2 || (d == b2 && ii < j2)) {
                b3 = b2; j3 = j2; b2 = d; j2 = ii;
            } else if (d < b3 || (d == b3 && ii < j3)) {
                b3 = d; j3 = ii;
            }
        }
        const int row = row0 + tid;
        if (row < NROWS) {
            if (b2 - b1 > DECIDE_GAP) {
                // unambiguous: fp16 error (<~0.8) plus ref-tie window can't flip
                g_top3[row] = make_int4(j1, j1, j1, 1);
            } else {
                int a = j1, b = j2, c = j3, t;
                if (a > b) { t = a; a = b; b = t; }
                if (b > c) { t = b; b = c; c = t; }
                if (a > b) { t = a; a = b; b = t; }
                g_top3[row] = make_int4(a, b, c, 0);
            }
        }
    }
}

// ---- phase 2: decided -> gather; ambiguous -> exact fp64 + verified tie rule ----
__global__ __launch_bounds__(128, 8)
void refine_kernel(const float* __restrict__ x, const float* __restrict__ cb,
                   float* __restrict__ zq, float* __restrict__ idx_out,
                   int NROWS, int write_idx)
{
    const int warp = threadIdx.x >> 5;
    const int lane = threadIdx.x & 31;
    const int row = blockIdx.x * 4 + warp;
    if (row >= NROWS) return;

    const int4 cand = g_top3[row];
    int chosen;

    if (cand.w) {
        chosen = cand.x;               // decided in phase 1
    } else {
        const float* xp = x + (size_t)row * C_DIM + lane * 8;
        float4 xa = *(const float4*)(xp);
        float4 xb = *(const float4*)(xp + 4);
        const float xs[8] = {xa.x, xa.y, xa.z, xa.w, xb.x, xb.y, xb.z, xb.w};

        double d[3];
        const int ci[3] = {cand.x, cand.y, cand.z};
#pragma unroll
        for (int q = 0; q < 3; ++q) {
            const float* ep = cb + (size_t)ci[q] * C_DIM + lane * 8;
            float4 ea = *(const float4*)(ep);
            float4 eb = *(const float4*)(ep + 4);
            const float es[8] = {ea.x, ea.y, ea.z, ea.w, eb.x, eb.y, eb.z, eb.w};
            double s0 = 0.0, s1 = 0.0;   // two chains to halve DFMA latency
#pragma unroll
            for (int t = 0; t < 4; ++t) {
                double df0 = (double)xs[2 * t]     - (double)es[2 * t];
                double df1 = (double)xs[2 * t + 1] - (double)es[2 * t + 1];
                s0 = fma(df0, df0, s0);
                s1 = fma(df1, df1, s1);
            }
            d[q] = s0 + s1;
        }
#pragma unroll
        for (int o = 16; o > 0; o >>= 1) {
#pragma unroll
            for (int q = 0; q < 3; ++q)
                d[q] += __shfl_down_sync(0xffffffffu, d[q], o);
        }
        if (lane == 0) {
            // ascending index order; replace only on strict (non-tie) improvement
            int bidx = ci[0];
            double bval = d[0];
#pragma unroll
            for (int q = 1; q < 3; ++q) {
                float f1 = (float)bval, f2 = (float)d[q];
                bool tie = (f1 == f2) || (fabs(d[q] - bval) < (double)TIE_GUARD);
                if (!tie && d[q] < bval) { bval = d[q]; bidx = ci[q]; }
            }
            chosen = bidx;
        }
        chosen = __shfl_sync(0xffffffffu, chosen, 0);
    }

    const float* ep = cb + (size_t)chosen * C_DIM + lane * 8;
    float* op = zq + (size_t)row * C_DIM + lane * 8;
    *(float4*)(op)     = *(const float4*)(ep);
    *(float4*)(op + 4) = *(const float4*)(ep + 4);

    if (write_idx && lane == 0) idx_out[row] = (float)chosen;
}

extern "C" void kernel_launch(void* const* d_in, const int* in_sizes, int n_in,
                              void* d_out, int out_size) {
    const float* x  = (const float*)d_in[0];
    const float* cb = (const float*)d_in[1];
    float* out = (float*)d_out;

    const int NROWS = in_sizes[0] / C_DIM;
    const int K     = in_sizes[1] / C_DIM;

    prep_cb<<<(K + 7) / 8, 256>>>(cb, K);

    cudaFuncSetAttribute(vq_main, cudaFuncAttributeMaxDynamicSharedMemorySize, SM_TOTAL);
    vq_main<<<(NROWS + TILE_M - 1) / TILE_M, NTHREADS, SM_TOTAL>>>(x, NROWS, K);

    const int write_idx = (out_size >= NROWS * C_DIM + NROWS) ? 1 : 0;
    refine_kernel<<<(NROWS + 3) / 4, 128>>>(x, cb, out, out + (size_t)NROWS * C_DIM,
                                            NROWS, write_idx);
}